// round 2
// baseline (speedup 1.0000x reference)
#include <cuda_runtime.h>
#include <math.h>

#define B_ROWS 16384
#define D_DIM  4096
#define H_DIM  128
#define E_DIM  64
#define NS     5

static constexpr float P_DROP = 0.3f;
static constexpr float SCALE  = (float)(1.0 / 0.7);   // exact f32 of double 1/0.7, matches jax
static constexpr float UNC_T  = 0.3f;

#define BM 128
#define BN 128
#define BK 16
#define TM 8
#define TN 8
#define NTHREADS 256

// dynamic smem layout (floats):
//   sH  : [128][129]            = 16512
//   sW2 : [128][64]             =  8192
//   sB2 : [64]                  =    64
// As/Bs for GEMM1 alias the sH region (needs 16*128*2 = 4096 floats).
#define SH_FLOATS   (128 * 129)
#define SW2_OFF     SH_FLOATS
#define SB2_OFF     (SH_FLOATS + 128 * 64)
#define SMEM_FLOATS (SB2_OFF + 64)
#define SMEM_BYTES  (SMEM_FLOATS * 4)

__global__ __launch_bounds__(NTHREADS, 1)
void bayes_route_kernel(const float* __restrict__ x,
                        const float* __restrict__ W1,
                        const float* __restrict__ b1,
                        const float* __restrict__ W2,
                        const float* __restrict__ b2,
                        const float* __restrict__ m1u,
                        const float* __restrict__ m2u,
                        float* __restrict__ out)
{
    extern __shared__ __align__(16) float smem[];
    float* sH  = smem;                 // [128][129]
    float* sW2 = smem + SW2_OFF;       // [128][64]
    float* sB2 = smem + SB2_OFF;       // [64]
    float* As  = smem;                 // [BK][BM], aliases sH (phase-separated)
    float* Bs  = smem + BK * BM;       // [BK][BN]

    const int tid = threadIdx.x;
    const int tx  = tid & 15;          // 0..15
    const int ty  = tid >> 4;          // 0..15
    const int rowBase = blockIdx.x * BM;

    // ---- preload W2, b2 into smem (phase-2 operands; untouched by As/Bs) ----
    {
        const float4* w2v = (const float4*)W2;
        float4* sv = (float4*)sW2;
        #pragma unroll
        for (int i = tid; i < (H_DIM * E_DIM) / 4; i += NTHREADS) sv[i] = w2v[i];
        if (tid < E_DIM) sB2[tid] = b2[tid];
    }
    // b1 slice for this thread's output columns
    float rb1[TN];
    #pragma unroll
    for (int j = 0; j < TN; j++) rb1[j] = b1[tx * TN + j];

    // =========================== Phase 1: h = relu(x@W1+b1) ===========================
    float acc[TM][TN];
    #pragma unroll
    for (int i = 0; i < TM; i++)
        #pragma unroll
        for (int j = 0; j < TN; j++) acc[i][j] = 0.f;

    const float* xblk = x + (size_t)rowBase * D_DIM;

    for (int kt = 0; kt < D_DIM; kt += BK) {
        __syncthreads();   // protect As/Bs (also orders vs sW2 preload first iter)
        // x tile -> As[k][m] (transposed store)
        #pragma unroll
        for (int i = 0; i < 2; i++) {
            int slot = tid * 2 + i;            // 0..511
            int m  = slot >> 2;
            int k4 = (slot & 3) * 4;
            float4 v = *(const float4*)(xblk + (size_t)m * D_DIM + kt + k4);
            As[(k4 + 0) * BM + m] = v.x;
            As[(k4 + 1) * BM + m] = v.y;
            As[(k4 + 2) * BM + m] = v.z;
            As[(k4 + 3) * BM + m] = v.w;
        }
        // W1 tile -> Bs[k][n]
        #pragma unroll
        for (int i = 0; i < 2; i++) {
            int slot = tid * 2 + i;
            int k  = slot >> 5;
            int n4 = (slot & 31) * 4;
            *(float4*)(Bs + k * BN + n4) =
                *(const float4*)(W1 + (size_t)(kt + k) * H_DIM + n4);
        }
        __syncthreads();
        #pragma unroll
        for (int k = 0; k < BK; k++) {
            float a[TM], bb[TN];
            #pragma unroll
            for (int i = 0; i < TM; i++) a[i]  = As[k * BM + ty * TM + i];
            #pragma unroll
            for (int j = 0; j < TN; j++) bb[j] = Bs[k * BN + tx * TN + j];
            #pragma unroll
            for (int i = 0; i < TM; i++)
                #pragma unroll
                for (int j = 0; j < TN; j++)
                    acc[i][j] = fmaf(a[i], bb[j], acc[i][j]);
        }
    }
    __syncthreads();   // done reading As/Bs; sH overwrite is now safe
    #pragma unroll
    for (int i = 0; i < TM; i++) {
        int r = ty * TM + i;
        #pragma unroll
        for (int j = 0; j < TN; j++) {
            float h = acc[i][j] + rb1[j];
            sH[r * 129 + tx * TN + j] = fmaxf(h, 0.f);
        }
    }
    __syncthreads();

    // =========================== Phase 2: samples, softmax, stats ===========================
    const int r    = tid >> 1;          // row within tile, 0..127
    const int half = tid & 1;           // e-half
    const int e0   = half * 32;
    const int grow = rowBase + r;
    const float* hrow = sH + r * 129;

    float sumL[32], sumP[32], sumP2[32];
    #pragma unroll
    for (int e = 0; e < 32; e++) { sumL[e] = 0.f; sumP[e] = 0.f; sumP2[e] = 0.f; }

    for (int s = 0; s < NS; s++) {
        float lg[32];
        #pragma unroll
        for (int e = 0; e < 32; e++) lg[e] = sB2[e0 + e];

        const float4* m1p = (const float4*)(m1u + ((size_t)s * B_ROWS + grow) * H_DIM);
        #pragma unroll 4
        for (int k4 = 0; k4 < 32; k4++) {
            float4 m4 = m1p[k4];
            float mm[4] = {m4.x, m4.y, m4.z, m4.w};
            #pragma unroll
            for (int j = 0; j < 4; j++) {
                int k = k4 * 4 + j;
                float m  = (mm[j] >= P_DROP) ? SCALE : 0.f;
                float hm = hrow[k] * m;
                const float* w2k = sW2 + k * E_DIM + e0;
                #pragma unroll
                for (int e = 0; e < 32; e++)
                    lg[e] = fmaf(hm, w2k[e], lg[e]);
            }
        }
        // mask2, accumulate logits, softmax over 64 (pairwise with partner lane)
        const float* m2p = m2u + ((size_t)s * B_ROWS + grow) * E_DIM + e0;
        float mx = -1e30f;
        #pragma unroll
        for (int e = 0; e < 32; e++) {
            float m2 = (m2p[e] >= P_DROP) ? SCALE : 0.f;
            lg[e] *= m2;
            sumL[e] += lg[e];
            mx = fmaxf(mx, lg[e]);
        }
        mx = fmaxf(mx, __shfl_xor_sync(0xFFFFFFFFu, mx, 1));
        float se = 0.f;
        #pragma unroll
        for (int e = 0; e < 32; e++) { lg[e] = expf(lg[e] - mx); se += lg[e]; }
        se += __shfl_xor_sync(0xFFFFFFFFu, se, 1);
        float inv = 1.f / se;
        #pragma unroll
        for (int e = 0; e < 32; e++) {
            float pe = lg[e] * inv;
            sumP[e]  += pe;
            sumP2[e]  = fmaf(pe, pe, sumP2[e]);
        }
    }

    // probs of mean logits
    float p[32];
    float mx = -1e30f;
    #pragma unroll
    for (int e = 0; e < 32; e++) { p[e] = sumL[e] * 0.2f; mx = fmaxf(mx, p[e]); }
    mx = fmaxf(mx, __shfl_xor_sync(0xFFFFFFFFu, mx, 1));
    float se = 0.f;
    #pragma unroll
    for (int e = 0; e < 32; e++) { p[e] = expf(p[e] - mx); se += p[e]; }
    se += __shfl_xor_sync(0xFFFFFFFFu, se, 1);
    float inv = 1.f / se;
    #pragma unroll
    for (int e = 0; e < 32; e++) p[e] *= inv;

    // uncertainty: mean over E of ddof=1 std over samples
    float us = 0.f;
    #pragma unroll
    for (int e = 0; e < 32; e++) {
        float mean = sumP[e] * 0.2f;
        float var  = (sumP2[e] - 5.f * mean * mean) * 0.25f;
        us += sqrtf(fmaxf(var, 0.f));
    }
    us += __shfl_xor_sync(0xFFFFFFFFu, us, 1);
    float unc = us * (1.f / 64.f);

    // top-4 over 64 probs (split across lane pair); ties -> lower index (matches lax.top_k)
    float fv[4];
    int   fi[4];
    #pragma unroll
    for (int t = 0; t < 4; t++) {
        float bv = -1.f;
        int   bi = 1 << 20;
        #pragma unroll
        for (int e = 0; e < 32; e++) {
            if (p[e] > bv) { bv = p[e]; bi = e0 + e; }
        }
        float ov = __shfl_xor_sync(0xFFFFFFFFu, bv, 1);
        int   oi = __shfl_xor_sync(0xFFFFFFFFu, bi, 1);
        if (ov > bv || (ov == bv && oi < bi)) { bv = ov; bi = oi; }
        fv[t] = bv; fi[t] = bi;
        #pragma unroll
        for (int e = 0; e < 32; e++)
            if (e0 + e == bi) p[e] = -2.f;
    }

    if (half == 0) {
        bool uncertain = unc > UNC_T;
        float* oIdx = out;
        float* oP   = out + (size_t)B_ROWS * 4;
        float* oU   = out + (size_t)B_ROWS * 8;
        oIdx[grow * 4 + 0] = (float)fi[0];
        oIdx[grow * 4 + 1] = (float)fi[1];
        oIdx[grow * 4 + 2] = uncertain ? (float)fi[2] : -1.f;
        oIdx[grow * 4 + 3] = uncertain ? (float)fi[3] : -1.f;
        oP[grow * 4 + 0] = fv[0];
        oP[grow * 4 + 1] = fv[1];
        oP[grow * 4 + 2] = uncertain ? fv[2] : 0.f;
        oP[grow * 4 + 3] = uncertain ? fv[3] : 0.f;
        oU[grow] = unc;
    }
}

extern "C" void kernel_launch(void* const* d_in, const int* in_sizes, int n_in,
                              void* d_out, int out_size)
{
    const float* x   = (const float*)d_in[0];
    const float* W1  = (const float*)d_in[1];
    const float* b1  = (const float*)d_in[2];
    const float* W2  = (const float*)d_in[3];
    const float* b2  = (const float*)d_in[4];
    const float* m1u = (const float*)d_in[5];
    const float* m2u = (const float*)d_in[6];
    float* out = (float*)d_out;

    cudaFuncSetAttribute(bayes_route_kernel,
                         cudaFuncAttributeMaxDynamicSharedMemorySize, SMEM_BYTES);
    bayes_route_kernel<<<B_ROWS / BM, NTHREADS, SMEM_BYTES>>>(
        x, W1, b1, W2, b2, m1u, m2u, out);
}

// round 3
// speedup vs baseline: 1.3575x; 1.3575x over previous
#include <cuda_runtime.h>
#include <math.h>

#define B_ROWS 16384
#define D_DIM  4096
#define H_DIM  128
#define E_DIM  64
#define NS     5

static constexpr float P_DROP = 0.3f;
static constexpr float SCALE  = (float)(1.0 / 0.7);
static constexpr float UNC_T  = 0.3f;

#define NT 256
#define BM 128
#define BK 32

// ---- shared memory layout (float offsets) ----
#define SH_PITCH 132
#define OFF_SH   0
#define SH_SIZE  (128 * SH_PITCH)          // 16896  (h, row-major)
#define OFF_HM   SH_SIZE                   // masked-h transposed [k][r], pitch 132
#define HM_SIZE  (128 * SH_PITCH)
#define OFF_AS   OFF_HM                    // phase-1 A tile aliases hM
#define AS_SIZE  (BK * SH_PITCH)           // 4224
#define OFF_BS   (OFF_AS + AS_SIZE)        // phase-1 B tile
#define OFF_W2   (OFF_HM + HM_SIZE)        // 33792
#define OFF_B2   (OFF_W2 + H_DIM * E_DIM)  // 41984
#define SMEM_FLOATS (OFF_B2 + 64)
#define SMEM_BYTES  (SMEM_FLOATS * 4)

typedef unsigned long long u64;

__device__ __forceinline__ u64 pack2(float a) {
    u64 r;
    asm("mov.b64 %0, {%1, %1};" : "=l"(r) : "r"(__float_as_uint(a)));
    return r;
}
__device__ __forceinline__ u64 pack2f(float a, float b) {
    u64 r;
    asm("mov.b64 %0, {%1, %2};" : "=l"(r) : "r"(__float_as_uint(a)), "r"(__float_as_uint(b)));
    return r;
}
__device__ __forceinline__ void unpack2(u64 v, float& a, float& b) {
    unsigned lo, hi;
    asm("mov.b64 {%0, %1}, %2;" : "=r"(lo), "=r"(hi) : "l"(v));
    a = __uint_as_float(lo);
    b = __uint_as_float(hi);
}
__device__ __forceinline__ void fma2(u64& d, u64 a, u64 b) {
    asm("fma.rn.f32x2 %0, %1, %2, %0;" : "+l"(d) : "l"(a), "l"(b));
}

__global__ __launch_bounds__(NT, 1)
void bayes_route_kernel(const float* __restrict__ x,
                        const float* __restrict__ W1,
                        const float* __restrict__ b1,
                        const float* __restrict__ W2,
                        const float* __restrict__ b2,
                        const float* __restrict__ m1u,
                        const float* __restrict__ m2u,
                        float* __restrict__ out)
{
    extern __shared__ __align__(16) float smem[];
    float* sH  = smem + OFF_SH;
    float* hM  = smem + OFF_HM;
    float* As  = smem + OFF_AS;
    float* Bs  = smem + OFF_BS;
    float* sW2 = smem + OFF_W2;
    float* sB2 = smem + OFF_B2;

    const int tid = threadIdx.x;
    const int tx  = tid & 15;     // 0..15
    const int ty  = tid >> 4;     // 0..15
    const int rowBase = blockIdx.x * BM;

    // ---- preload W2, b2 (phase-2 operands; region untouched by As/Bs) ----
    {
        const float4* w2v = (const float4*)W2;
        float4* sv = (float4*)sW2;
        #pragma unroll
        for (int i = tid; i < (H_DIM * E_DIM) / 4; i += NT) sv[i] = w2v[i];
        if (tid < E_DIM) sB2[tid] = b2[tid];
    }

    // =========================== Phase 1: h = relu(x@W1 + b1) ===========================
    // 128x128 tile, BK=32, 8x8 register tile per thread, f32x2 packed accumulators.
    u64 acc[8][4];
    #pragma unroll
    for (int i = 0; i < 8; i++)
        #pragma unroll
        for (int j = 0; j < 4; j++) acc[i][j] = 0ull;

    const float* xp = x + (size_t)rowBase * D_DIM;

    // per-thread load slots (4 float4 of x, 4 float4 of W1 per iteration)
    int xm[4], xk4[4], wk[4], wn4[4];
    #pragma unroll
    for (int i = 0; i < 4; i++) {
        int f = tid + (i << 8);
        xm[i]  = f >> 3;            // row within tile (0..127)
        xk4[i] = (f & 7) * 4;       // k offset within BK
        wk[i]  = f >> 5;            // k row (0..31)
        wn4[i] = (f & 31) * 4;      // n offset
    }

    float4 px[4], pw[4];
    #pragma unroll
    for (int i = 0; i < 4; i++) {
        px[i] = *(const float4*)(xp + (size_t)xm[i] * D_DIM + xk4[i]);
        pw[i] = *(const float4*)(W1 + (size_t)wk[i] * H_DIM + wn4[i]);
    }

    const int nIter = D_DIM / BK;   // 128
    for (int kt = 0; kt < nIter; kt++) {
        __syncthreads();            // previous compute done reading As/Bs
        // store prefetched tiles: As transposed [k][m] (pitch 132), Bs row-major
        #pragma unroll
        for (int i = 0; i < 4; i++) {
            const float* pf = (const float*)&px[i];
            int m = xm[i], k4 = xk4[i];
            As[(k4 + 0) * SH_PITCH + m] = pf[0];
            As[(k4 + 1) * SH_PITCH + m] = pf[1];
            As[(k4 + 2) * SH_PITCH + m] = pf[2];
            As[(k4 + 3) * SH_PITCH + m] = pf[3];
            *(float4*)(Bs + wk[i] * H_DIM + wn4[i]) = pw[i];
        }
        __syncthreads();
        // prefetch next tile while computing
        if (kt + 1 < nIter) {
            int kb = (kt + 1) * BK;
            #pragma unroll
            for (int i = 0; i < 4; i++) {
                px[i] = *(const float4*)(xp + (size_t)xm[i] * D_DIM + kb + xk4[i]);
                pw[i] = *(const float4*)(W1 + (size_t)(kb + wk[i]) * H_DIM + wn4[i]);
            }
        }
        #pragma unroll 8
        for (int k = 0; k < BK; k++) {
            float4 a0 = *(const float4*)(As + k * SH_PITCH + ty * 8);
            float4 a1 = *(const float4*)(As + k * SH_PITCH + ty * 8 + 4);
            ulonglong2 bq0 = *(const ulonglong2*)(Bs + k * H_DIM + tx * 8);
            ulonglong2 bq1 = *(const ulonglong2*)(Bs + k * H_DIM + tx * 8 + 4);
            float av[8] = {a0.x, a0.y, a0.z, a0.w, a1.x, a1.y, a1.z, a1.w};
            #pragma unroll
            for (int i = 0; i < 8; i++) {
                u64 aa = pack2(av[i]);
                fma2(acc[i][0], aa, bq0.x);
                fma2(acc[i][1], aa, bq0.y);
                fma2(acc[i][2], aa, bq1.x);
                fma2(acc[i][3], aa, bq1.y);
            }
        }
    }
    __syncthreads();   // done with As/Bs; hM region reusable

    // epilogue: bias + relu -> sH row-major
    {
        float4 b1a = *(const float4*)(b1 + tx * 8);
        float4 b1b = *(const float4*)(b1 + tx * 8 + 4);
        float bf[8] = {b1a.x, b1a.y, b1a.z, b1a.w, b1b.x, b1b.y, b1b.z, b1b.w};
        #pragma unroll
        for (int i = 0; i < 8; i++) {
            int rr = ty * 8 + i;
            float h[8];
            unpack2(acc[i][0], h[0], h[1]);
            unpack2(acc[i][1], h[2], h[3]);
            unpack2(acc[i][2], h[4], h[5]);
            unpack2(acc[i][3], h[6], h[7]);
            #pragma unroll
            for (int j = 0; j < 8; j++) h[j] = fmaxf(h[j] + bf[j], 0.f);
            *(float4*)(sH + rr * SH_PITCH + tx * 8)     = make_float4(h[0], h[1], h[2], h[3]);
            *(float4*)(sH + rr * SH_PITCH + tx * 8 + 4) = make_float4(h[4], h[5], h[6], h[7]);
        }
    }
    __syncthreads();

    // =========================== Phase 2: 5 samples, softmax, stats ===========================
    const int e0 = tx * 4;          // 4 experts per thread
    const int ro = ty * 8;          // 8 rows per thread

    float sumL[8][4], sumP[8][4], sumP2[8][4];
    #pragma unroll
    for (int i = 0; i < 8; i++)
        #pragma unroll
        for (int j = 0; j < 4; j++) { sumL[i][j] = 0.f; sumP[i][j] = 0.f; sumP2[i][j] = 0.f; }

    const u64 ib0 = pack2f(sB2[e0], sB2[e0 + 1]);
    const u64 ib1 = pack2f(sB2[e0 + 2], sB2[e0 + 3]);

    const int mr  = tid & 127;      // masking: row
    const int mkh = tid >> 7;       // masking: k half (0/1)

    for (int s = 0; s < NS; s++) {
        // ---- build masked transposed tile hM[k][r] ----
        __syncthreads();  // previous GEMM done reading hM
        {
            const float4* mrow = (const float4*)(m1u +
                ((size_t)s * B_ROWS + rowBase + mr) * H_DIM + mkh * 64);
            const float4* hrow = (const float4*)(sH + mr * SH_PITCH + mkh * 64);
            #pragma unroll
            for (int q = 0; q < 16; q++) {
                float4 mu = mrow[q];
                float4 hv = hrow[q];
                int kb = mkh * 64 + q * 4;
                hM[(kb + 0) * SH_PITCH + mr] = (mu.x >= P_DROP) ? hv.x * SCALE : 0.f;
                hM[(kb + 1) * SH_PITCH + mr] = (mu.y >= P_DROP) ? hv.y * SCALE : 0.f;
                hM[(kb + 2) * SH_PITCH + mr] = (mu.z >= P_DROP) ? hv.z * SCALE : 0.f;
                hM[(kb + 3) * SH_PITCH + mr] = (mu.w >= P_DROP) ? hv.w * SCALE : 0.f;
            }
        }
        __syncthreads();

        // ---- GEMM: logits[128x64] = hM^T @ W2, 8 rows x 4 experts per thread ----
        u64 lacc[8][2];
        #pragma unroll
        for (int i = 0; i < 8; i++) { lacc[i][0] = ib0; lacc[i][1] = ib1; }

        #pragma unroll 4
        for (int k = 0; k < H_DIM; k++) {
            float4 a0 = *(const float4*)(hM + k * SH_PITCH + ro);
            float4 a1 = *(const float4*)(hM + k * SH_PITCH + ro + 4);
            ulonglong2 bb = *(const ulonglong2*)(sW2 + k * E_DIM + e0);
            float av[8] = {a0.x, a0.y, a0.z, a0.w, a1.x, a1.y, a1.z, a1.w};
            #pragma unroll
            for (int i = 0; i < 8; i++) {
                u64 aa = pack2(av[i]);
                fma2(lacc[i][0], aa, bb.x);
                fma2(lacc[i][1], aa, bb.y);
            }
        }

        // ---- mask2, per-row softmax (reduce over 16 tx lanes), accumulate stats ----
        #pragma unroll
        for (int i = 0; i < 8; i++) {
            size_t row = (size_t)rowBase + ro + i;
            float4 mu = *(const float4*)(m2u + ((size_t)s * B_ROWS + row) * E_DIM + e0);
            float l[4];
            unpack2(lacc[i][0], l[0], l[1]);
            unpack2(lacc[i][1], l[2], l[3]);
            l[0] *= (mu.x >= P_DROP) ? SCALE : 0.f;
            l[1] *= (mu.y >= P_DROP) ? SCALE : 0.f;
            l[2] *= (mu.z >= P_DROP) ? SCALE : 0.f;
            l[3] *= (mu.w >= P_DROP) ? SCALE : 0.f;
            float mx = fmaxf(fmaxf(l[0], l[1]), fmaxf(l[2], l[3]));
            #pragma unroll
            for (int j = 0; j < 4; j++) sumL[i][j] += l[j];
            #pragma unroll
            for (int off = 1; off < 16; off <<= 1)
                mx = fmaxf(mx, __shfl_xor_sync(0xFFFFFFFFu, mx, off));
            float ex[4];
            float ss = 0.f;
            #pragma unroll
            for (int j = 0; j < 4; j++) { ex[j] = __expf(l[j] - mx); ss += ex[j]; }
            #pragma unroll
            for (int off = 1; off < 16; off <<= 1)
                ss += __shfl_xor_sync(0xFFFFFFFFu, ss, off);
            float inv = 1.f / ss;
            #pragma unroll
            for (int j = 0; j < 4; j++) {
                float pe = ex[j] * inv;
                sumP[i][j] += pe;
                sumP2[i][j] = fmaf(pe, pe, sumP2[i][j]);
            }
        }
    }

    // =========================== Final: mean softmax, uncertainty, top-4 ===========================
    #pragma unroll
    for (int i = 0; i < 8; i++) {
        // probs of mean logits
        float p[4];
        float mx = -1e30f;
        #pragma unroll
        for (int j = 0; j < 4; j++) { p[j] = sumL[i][j] * 0.2f; mx = fmaxf(mx, p[j]); }
        #pragma unroll
        for (int off = 1; off < 16; off <<= 1)
            mx = fmaxf(mx, __shfl_xor_sync(0xFFFFFFFFu, mx, off));
        float ss = 0.f;
        #pragma unroll
        for (int j = 0; j < 4; j++) { p[j] = __expf(p[j] - mx); ss += p[j]; }
        #pragma unroll
        for (int off = 1; off < 16; off <<= 1)
            ss += __shfl_xor_sync(0xFFFFFFFFu, ss, off);
        float inv = 1.f / ss;
        #pragma unroll
        for (int j = 0; j < 4; j++) p[j] *= inv;

        // uncertainty: mean over e of ddof=1 std over samples
        float us = 0.f;
        #pragma unroll
        for (int j = 0; j < 4; j++) {
            float mean = sumP[i][j] * 0.2f;
            float var  = (sumP2[i][j] - 5.f * mean * mean) * 0.25f;
            us += sqrtf(fmaxf(var, 0.f));
        }
        #pragma unroll
        for (int off = 1; off < 16; off <<= 1)
            us += __shfl_xor_sync(0xFFFFFFFFu, us, off);
        float unc = us * (1.f / 64.f);

        // top-4 over 64 experts (distributed across 16 tx lanes); ties -> lower index
        float fv[4];
        int   fi[4];
        #pragma unroll
        for (int t = 0; t < 4; t++) {
            float bv = p[0]; int bi = e0;
            #pragma unroll
            for (int j = 1; j < 4; j++)
                if (p[j] > bv) { bv = p[j]; bi = e0 + j; }
            #pragma unroll
            for (int off = 1; off < 16; off <<= 1) {
                float ov = __shfl_xor_sync(0xFFFFFFFFu, bv, off);
                int   oi = __shfl_xor_sync(0xFFFFFFFFu, bi, off);
                if (ov > bv || (ov == bv && oi < bi)) { bv = ov; bi = oi; }
            }
            fv[t] = bv; fi[t] = bi;
            #pragma unroll
            for (int j = 0; j < 4; j++)
                if (e0 + j == bi) p[j] = -2.f;
        }

        if (tx == 0) {
            size_t grow = (size_t)rowBase + ro + i;
            bool uncertain = unc > UNC_T;
            float* oIdx = out;
            float* oP   = out + (size_t)B_ROWS * 4;
            float* oU   = out + (size_t)B_ROWS * 8;
            oIdx[grow * 4 + 0] = (float)fi[0];
            oIdx[grow * 4 + 1] = (float)fi[1];
            oIdx[grow * 4 + 2] = uncertain ? (float)fi[2] : -1.f;
            oIdx[grow * 4 + 3] = uncertain ? (float)fi[3] : -1.f;
            oP[grow * 4 + 0] = fv[0];
            oP[grow * 4 + 1] = fv[1];
            oP[grow * 4 + 2] = uncertain ? fv[2] : 0.f;
            oP[grow * 4 + 3] = uncertain ? fv[3] : 0.f;
            oU[grow] = unc;
        }
    }
}

extern "C" void kernel_launch(void* const* d_in, const int* in_sizes, int n_in,
                              void* d_out, int out_size)
{
    (void)in_sizes; (void)n_in; (void)out_size;
    const float* x   = (const float*)d_in[0];
    const float* W1  = (const float*)d_in[1];
    const float* b1  = (const float*)d_in[2];
    const float* W2  = (const float*)d_in[3];
    const float* b2  = (const float*)d_in[4];
    const float* m1u = (const float*)d_in[5];
    const float* m2u = (const float*)d_in[6];
    float* out = (float*)d_out;

    cudaFuncSetAttribute(bayes_route_kernel,
                         cudaFuncAttributeMaxDynamicSharedMemorySize, SMEM_BYTES);
    bayes_route_kernel<<<B_ROWS / BM, NT, SMEM_BYTES>>>(
        x, W1, b1, W2, b2, m1u, m2u, out);
}